// round 8
// baseline (speedup 1.0000x reference)
#include <cuda_runtime.h>

#define NXC 128
#define NYC 128
#define NZC 64
#define BC  2
#define TC  12

constexpr int MCELL = NXC * NYC * NZC;   // 1,048,576
constexpr int NCELL = BC * MCELL;        // 2,097,152
constexpr int M4  = MCELL / 4;           // float4 cells per batch
constexpr int F4  = NCELL / 4;           // float4 stride between fields
constexpr int SX4 = NYC * NZC / 4;       // 2048
constexpr int SY4 = NZC / 4;             // 16

constexpr int XR = 4;                    // x rows marched per block

constexpr float DTc   = 1e-3f;
constexpr float INVH  = 0.1f;
constexpr float BULK  = 1.0f - 0.01f * 1e-3f;
constexpr float H     = 10.0f;
constexpr float SRC_Z = 320.0f;
constexpr float IS_XY = 1.0f / 800.0f;
constexpr float IS_Z  = 1.0f / 200.0f;

// All 9 state fields behind ONE base pointer: field f at offset f*NCELL.
// 0:vx 1:vy 2:vz 3:sxx 4:syy 5:szz 6:sxy 7:sxz 8:syz
__device__ float g_state[9][NCELL];

// ---- float4 helpers -------------------------------------------------------
__device__ __forceinline__ float4 operator+(float4 a, float4 b) {
    return make_float4(a.x + b.x, a.y + b.y, a.z + b.z, a.w + b.w);
}
__device__ __forceinline__ float4 operator-(float4 a, float4 b) {
    return make_float4(a.x - b.x, a.y - b.y, a.z - b.z, a.w - b.w);
}
__device__ __forceinline__ float4 operator*(float s, float4 a) {
    return make_float4(s * a.x, s * a.y, s * a.z, s * a.w);
}
__device__ __forceinline__ float4 operator*(float4 a, float4 b) {
    return make_float4(a.x * b.x, a.y * b.y, a.z * b.z, a.w * b.w);
}

__device__ __forceinline__ float4 shift_fwd(float4 v, int k4) {
    float n = __shfl_down_sync(0xffffffffu, v.x, 1, 16);
    if (k4 == 15) n = v.w;
    return make_float4(v.y, v.z, v.w, n);
}
__device__ __forceinline__ float4 shift_bwd(float4 v, int k4) {
    float p = __shfl_up_sync(0xffffffffu, v.w, 1, 16);
    if (k4 == 0) p = v.x;
    return make_float4(p, v.x, v.y, v.z);
}

// ---- t=0: zero state + pure source injection into vz ----------------------
__global__ __launch_bounds__(256) void init_step_kernel(
    const float* __restrict__ rho, const float* __restrict__ damping,
    const float* __restrict__ traj)
{
    const int k4 = threadIdx.x;
    const int j  = blockIdx.x * 16 + threadIdx.y;
    const int i  = blockIdx.y;
    const int b  = blockIdx.z;
    const int mm4  = (i * NYC + j) * SY4 + k4;
    const int idx4 = b * M4 + mm4;

    float4* st = reinterpret_cast<float4*>(g_state);
    const float4 z4 = make_float4(0.f, 0.f, 0.f, 0.f);
    st[0 * F4 + idx4] = z4;
    st[1 * F4 + idx4] = z4;
    #pragma unroll
    for (int f = 3; f < 9; f++)
        st[f * F4 + idx4] = z4;

    const float xt = traj[(b * TC + 0) * 2 + 0];
    const float yt = traj[(b * TC + 0) * 2 + 1];
    const float xg = (i + 0.5f) * H, yg = (j + 0.5f) * H;
    const float axy = -((xg - xt) * (xg - xt) + (yg - yt) * (yg - yt)) * IS_XY;
    float s[4];
    #pragma unroll
    for (int c = 0; c < 4; c++) {
        float dz = (4 * k4 + c + 0.5f) * H - SRC_Z;
        float arg = axy - dz * dz * IS_Z;
        s[c] = (arg > -60.0f) ? __expf(arg) : 0.0f;
    }
    const float rinv = 1.0f / rho[0];
    const float4 damp = reinterpret_cast<const float4*>(damping)[mm4];
    const float4 fac = BULK * damp;
    st[2 * F4 + idx4] = ((DTc * rinv) * make_float4(s[0], s[1], s[2], s[3])) * fac;
}

// ---- stress update: marches XR x-rows DESCENDING, carrying v(x+1) ---------
__global__ __launch_bounds__(256, 4) void stress_step_kernel(
    const float* __restrict__ lam, const float* __restrict__ mu,
    const float* __restrict__ eta)
{
    const int k4 = threadIdx.x;
    const int j  = blockIdx.x * 16 + threadIdx.y;
    const int xs = blockIdx.y * XR;
    const int b  = blockIdx.z;
    const int base = b * M4 + j * SY4 + k4;

    const bool hy = (j + 1 < NYC);
    const int dy = hy ? SY4 : 0;

    const float lam0 = lam[0];
    const float mu0  = mu[0];
    const float me   = mu0 + eta[0];

    cudaGridDependencySynchronize();

    float4* st = reinterpret_cast<float4*>(g_state);

    // Carried v(x+1); seeded below on first iteration via clamp or preload.
    float4 vxN, vyN, vzN;
    const int xe = xs + XR - 1;
    if (xe + 1 < NXC) {
        const int idn = base + (xe + 1) * NYC * SY4;
        vxN = st[0 * F4 + idn];
        vyN = st[1 * F4 + idn];
        vzN = st[2 * F4 + idn];
    }

    #pragma unroll
    for (int r = XR - 1; r >= 0; --r) {
        const int x = xs + r;
        const int id = base + x * NYC * SY4;

        const float4 vxc  = st[0 * F4 + id];
        const float4 vyc  = st[1 * F4 + id];
        const float4 vzc  = st[2 * F4 + id];
        const float4 vx_y = st[0 * F4 + id + dy];
        const float4 vy_y = st[1 * F4 + id + dy];
        const float4 vz_y = st[2 * F4 + id + dy];
        const float4 sxx_o = st[3 * F4 + id];
        const float4 syy_o = st[4 * F4 + id];
        const float4 szz_o = st[5 * F4 + id];
        const float4 sxy_o = st[6 * F4 + id];
        const float4 sxz_o = st[7 * F4 + id];
        const float4 syz_o = st[8 * F4 + id];

        // x+1 neighbor: carried regs, clamped at the far edge.
        const float4 vx_x = (x + 1 < NXC) ? vxN : vxc;
        const float4 vy_x = (x + 1 < NXC) ? vyN : vyc;
        const float4 vz_x = (x + 1 < NXC) ? vzN : vzc;

        const float4 vx_z = shift_fwd(vxc, k4);
        const float4 vy_z = shift_fwd(vyc, k4);
        const float4 vz_z = shift_fwd(vzc, k4);

        const float4 exx = INVH * (vx_x - vxc);
        const float4 eyy = INVH * (vy_y - vyc);
        const float4 ezz = INVH * (vz_z - vzc);
        const float4 exy2 = INVH * ((vx_y - vxc) + (vy_x - vyc));
        const float4 exz2 = INVH * ((vx_z - vxc) + (vz_x - vzc));
        const float4 eyz2 = INVH * ((vy_z - vyc) + (vz_y - vzc));
        const float4 tr = exx + eyy + ezz;

        st[3 * F4 + id] = sxx_o + DTc * (lam0 * tr + (2.0f * mu0) * exx);
        st[4 * F4 + id] = syy_o + DTc * (lam0 * tr + (2.0f * mu0) * eyy);
        st[5 * F4 + id] = szz_o + DTc * (lam0 * tr + (2.0f * mu0) * ezz);
        st[6 * F4 + id] = sxy_o + (DTc * me) * exy2;
        st[7 * F4 + id] = sxz_o + (DTc * me) * exz2;
        st[8 * F4 + id] = syz_o + (DTc * me) * eyz2;

        vxN = vxc; vyN = vyc; vzN = vzc;   // carry center -> next (x-1) halo
    }
}

// ---- velocity update: marches XR x-rows ASCENDING, carrying s(x-1) --------
__global__ __launch_bounds__(256, 4) void velocity_step_kernel(
    const float* __restrict__ rho, const float* __restrict__ damping,
    const float* __restrict__ traj, int t, int write_out, float* __restrict__ out)
{
    const int k4 = threadIdx.x;
    const int j  = blockIdx.x * 16 + threadIdx.y;
    const int xs = blockIdx.y * XR;
    const int b  = blockIdx.z;
    const int base  = b * M4 + j * SY4 + k4;
    const int mbase = j * SY4 + k4;          // batch-free, for damping/out idx

    const bool ly = (j > 0);
    const int dy = ly ? SY4 : 0;

    // Prologue: input-only work.
    const float xt = traj[(b * TC + t) * 2 + 0];
    const float yt = traj[(b * TC + t) * 2 + 1];
    const float dy2 = ((j + 0.5f) * H - yt) * ((j + 0.5f) * H - yt);
    float zsq[4];
    #pragma unroll
    for (int c = 0; c < 4; c++) {
        float dz = (4 * k4 + c + 0.5f) * H - SRC_Z;
        zsq[c] = dz * dz;
    }
    const float rinv = 1.0f / rho[0];

    cudaGridDependencySynchronize();

    float4* st = reinterpret_cast<float4*>(g_state);

    // Carried x-1 stress (sxx, sxy, sxz); preload halo if xs > 0.
    float4 sxxP, sxyP, sxzP;
    if (xs > 0) {
        const int idp = base + (xs - 1) * NYC * SY4;
        sxxP = st[3 * F4 + idp];
        sxyP = st[6 * F4 + idp];
        sxzP = st[7 * F4 + idp];
    }

    #pragma unroll
    for (int r = 0; r < XR; ++r) {
        const int x = xs + r;
        const int id = base + x * NYC * SY4;

        const float4 sxxc = st[3 * F4 + id];
        const float4 syyc = st[4 * F4 + id];
        const float4 szzc = st[5 * F4 + id];
        const float4 sxyc = st[6 * F4 + id];
        const float4 sxzc = st[7 * F4 + id];
        const float4 syzc = st[8 * F4 + id];
        const float4 sxy_y = st[6 * F4 + id - dy];
        const float4 syy_y = st[4 * F4 + id - dy];
        const float4 syz_y = st[8 * F4 + id - dy];
        const float4 vx_old = st[0 * F4 + id];
        const float4 vy_old = st[1 * F4 + id];
        const float4 vz_old = st[2 * F4 + id];
        const float4 damp = reinterpret_cast<const float4*>(damping)
                                [mbase + x * NYC * SY4];

        const float4 sxx_x = (x > 0) ? sxxP : sxxc;
        const float4 sxy_x = (x > 0) ? sxyP : sxyc;
        const float4 sxz_x = (x > 0) ? sxzP : sxzc;

        const float4 sxz_z = shift_bwd(sxzc, k4);
        const float4 syz_z = shift_bwd(syzc, k4);
        const float4 szz_z = shift_bwd(szzc, k4);

        const float4 div_x = INVH * ((sxxc - sxx_x) + (sxyc - sxy_y) + (sxzc - sxz_z));
        const float4 div_y = INVH * ((sxyc - sxy_x) + (syyc - syy_y) + (syzc - syz_z));
        const float4 div_z = INVH * ((sxzc - sxz_x) + (syzc - syz_y) + (szzc - szz_z));

        const float xg = (x + 0.5f) * H;
        const float axy = -((xg - xt) * (xg - xt) + dy2) * IS_XY;
        float s[4];
        #pragma unroll
        for (int c = 0; c < 4; c++) {
            float arg = axy - zsq[c] * IS_Z;
            s[c] = (arg > -60.0f) ? __expf(arg) : 0.0f;
        }
        const float4 src = make_float4(s[0], s[1], s[2], s[3]);

        const float4 fac = BULK * damp;
        const float4 vx = (vx_old + (DTc * rinv) * div_x) * fac;
        const float4 vy = (vy_old + (DTc * rinv) * div_y) * fac;
        const float4 vz = (vz_old + (DTc * rinv) * (div_z + src)) * fac;

        st[0 * F4 + id] = vx;
        st[1 * F4 + id] = vy;
        st[2 * F4 + id] = vz;

        if (write_out) {
            float4* out4 = reinterpret_cast<float4*>(out);
            out4[id] = vz;
            float4 sm;
            sm.x = sqrtf(sxyc.x * sxyc.x + sxzc.x * sxzc.x + syzc.x * syzc.x + 1e-8f);
            sm.y = sqrtf(sxyc.y * sxyc.y + sxzc.y * sxzc.y + syzc.y * syzc.y + 1e-8f);
            sm.z = sqrtf(sxyc.z * sxyc.z + sxzc.z * sxzc.z + syzc.z * syzc.z + 1e-8f);
            sm.w = sqrtf(sxyc.w * sxyc.w + sxzc.w * sxzc.w + syzc.w * syzc.w + 1e-8f);
            out4[F4 + id] = sm;
        }

        sxxP = sxxc; sxyP = sxyc; sxzP = sxzc;   // carry center -> next halo
    }
}

// ---- PDL launch helper ----------------------------------------------------
template <typename... Args>
static void launch_pdl(void (*kern)(Args...), dim3 grd, dim3 blk, Args... args)
{
    cudaLaunchAttribute attr[1];
    attr[0].id = cudaLaunchAttributeProgrammaticStreamSerialization;
    attr[0].val.programmaticStreamSerializationAllowed = 1;
    cudaLaunchConfig_t cfg{};
    cfg.gridDim = grd;
    cfg.blockDim = blk;
    cfg.dynamicSmemBytes = 0;
    cfg.stream = 0;
    cfg.attrs = attr;
    cfg.numAttrs = 1;
    cudaLaunchKernelEx(&cfg, kern, args...);
}

extern "C" void kernel_launch(void* const* d_in, const int* in_sizes, int n_in,
                              void* d_out, int out_size)
{
    // metadata order: trajectory, grid_x, grid_y, grid_z, rho, mu, lam, eta, damping
    const float* traj    = (const float*)d_in[0];
    const float* rho     = (const float*)d_in[4];
    const float* mu      = (const float*)d_in[5];
    const float* lam     = (const float*)d_in[6];
    const float* eta     = (const float*)d_in[7];
    const float* damping = (const float*)d_in[8];
    float* out = (float*)d_out;

    dim3 blkI(16, 16, 1);
    dim3 grdI(NYC / 16, NXC, BC);
    init_step_kernel<<<grdI, blkI>>>(rho, damping, traj);

    dim3 blk(16, 16, 1);
    dim3 grd(NYC / 16, NXC / XR, BC);
    for (int t = 1; t < TC; t++) {
        launch_pdl(stress_step_kernel, grd, blk, lam, mu, eta);
        launch_pdl(velocity_step_kernel, grd, blk, rho, damping, traj, t,
                   (t == TC - 1) ? 1 : 0, out);
    }
}

// round 9
// speedup vs baseline: 1.0811x; 1.0811x over previous
#include <cuda_runtime.h>

#define NXC 128
#define NYC 128
#define NZC 64
#define BC  2
#define TC  12

constexpr int MCELL = NXC * NYC * NZC;   // 1,048,576
constexpr int NCELL = BC * MCELL;        // 2,097,152
constexpr int M4  = MCELL / 4;           // float4 cells per batch
constexpr int F4  = NCELL / 4;           // float4 stride between fields
constexpr int SX4 = NYC * NZC / 4;       // 2048
constexpr int SY4 = NZC / 4;             // 16

constexpr float DTc   = 1e-3f;
constexpr float INVH  = 0.1f;
constexpr float BULK  = 1.0f - 0.01f * 1e-3f;
constexpr float H     = 10.0f;
constexpr float SRC_Z = 320.0f;
constexpr float IS_XY = 1.0f / 800.0f;
constexpr float IS_Z  = 1.0f / 200.0f;

// All 9 state fields behind ONE base pointer: field f at offset f*NCELL.
// 0:vx 1:vy 2:vz 3:sxx 4:syy 5:szz 6:sxy 7:sxz 8:syz
__device__ float g_state[9][NCELL];

// ---- float4 helpers -------------------------------------------------------
__device__ __forceinline__ float4 operator+(float4 a, float4 b) {
    return make_float4(a.x + b.x, a.y + b.y, a.z + b.z, a.w + b.w);
}
__device__ __forceinline__ float4 operator-(float4 a, float4 b) {
    return make_float4(a.x - b.x, a.y - b.y, a.z - b.z, a.w - b.w);
}
__device__ __forceinline__ float4 operator*(float s, float4 a) {
    return make_float4(s * a.x, s * a.y, s * a.z, s * a.w);
}
__device__ __forceinline__ float4 operator*(float4 a, float4 b) {
    return make_float4(a.x * b.x, a.y * b.y, a.z * b.z, a.w * b.w);
}

// Forward z-shift: (v.y, v.z, v.w, next.x); clamp at domain top (k4==15).
__device__ __forceinline__ float4 shift_fwd(float4 v, int k4) {
    float n = __shfl_down_sync(0xffffffffu, v.x, 1, 16);
    if (k4 == 15) n = v.w;
    return make_float4(v.y, v.z, v.w, n);
}
// Backward z-shift: (prev.w, v.x, v.y, v.z); clamp at domain bottom (k4==0).
__device__ __forceinline__ float4 shift_bwd(float4 v, int k4) {
    float p = __shfl_up_sync(0xffffffffu, v.w, 1, 16);
    if (k4 == 0) p = v.x;
    return make_float4(p, v.x, v.y, v.z);
}

// ---- t=0: ONLY write vz = source injection --------------------------------
// (vx, vy and all stresses are compile-time zeros inside the FIRST-step
//  kernels below, and every field is overwritten there before any later read,
//  so no zero-fill of the other 8 fields is needed.)
__global__ __launch_bounds__(256) void init_step_kernel(
    const float* __restrict__ rho, const float* __restrict__ damping,
    const float* __restrict__ traj)
{
    const int k4 = threadIdx.x;
    const int j  = blockIdx.x * 16 + threadIdx.y;
    const int i  = blockIdx.y;
    const int b  = blockIdx.z;
    const int mm4  = (i * NYC + j) * SY4 + k4;
    const int idx4 = b * M4 + mm4;

    const float xt = traj[(b * TC + 0) * 2 + 0];
    const float yt = traj[(b * TC + 0) * 2 + 1];
    const float xg = (i + 0.5f) * H, yg = (j + 0.5f) * H;
    const float axy = -((xg - xt) * (xg - xt) + (yg - yt) * (yg - yt)) * IS_XY;
    float s[4];
    #pragma unroll
    for (int c = 0; c < 4; c++) {
        float dz = (4 * k4 + c + 0.5f) * H - SRC_Z;
        float arg = axy - dz * dz * IS_Z;
        s[c] = (arg > -60.0f) ? __expf(arg) : 0.0f;
    }
    const float rinv = 1.0f / rho[0];
    const float4 damp = reinterpret_cast<const float4*>(damping)[mm4];
    const float4 fac = BULK * damp;
    reinterpret_cast<float4*>(g_state)[2 * F4 + idx4] =
        ((DTc * rinv) * make_float4(s[0], s[1], s[2], s[3])) * fac;
}

// ---- stress update (forward differences) ----------------------------------
// FIRST: vx=vy=0 and all old stresses=0 -> only vz is read.
template <bool FIRST>
__global__ __launch_bounds__(256, 5) void stress_step_kernel(
    const float* __restrict__ lam, const float* __restrict__ mu,
    const float* __restrict__ eta)
{
    const int k4 = threadIdx.x;
    const int j  = blockIdx.x * 16 + threadIdx.y;
    const int i  = blockIdx.y;
    const int b  = blockIdx.z;
    const int idx4 = b * M4 + (i * NYC + j) * SY4 + k4;

    const bool hx = (i + 1 < NXC);
    const bool hy = (j + 1 < NYC);
    const int ix = hx ? idx4 + SX4 : idx4;
    const int iy = hy ? idx4 + SY4 : idx4;
    const float4 Z0 = make_float4(0.f, 0.f, 0.f, 0.f);

    // Prologue (state-independent).
    const float lam0 = lam[0];
    const float mu0  = mu[0];
    const float me   = mu0 + eta[0];

    cudaGridDependencySynchronize();

    float4* st = reinterpret_cast<float4*>(g_state);

    // Front-batched loads (zeros substituted at compile time for FIRST).
    const float4 vxc  = FIRST ? Z0 : st[0 * F4 + idx4];
    const float4 vyc  = FIRST ? Z0 : st[1 * F4 + idx4];
    const float4 vzc  = st[2 * F4 + idx4];
    const float4 vx_x = FIRST ? Z0 : st[0 * F4 + ix];
    const float4 vy_x = FIRST ? Z0 : st[1 * F4 + ix];
    const float4 vz_x = st[2 * F4 + ix];
    const float4 vx_y = FIRST ? Z0 : st[0 * F4 + iy];
    const float4 vy_y = FIRST ? Z0 : st[1 * F4 + iy];
    const float4 vz_y = st[2 * F4 + iy];
    const float4 sxx_o = FIRST ? Z0 : st[3 * F4 + idx4];
    const float4 syy_o = FIRST ? Z0 : st[4 * F4 + idx4];
    const float4 szz_o = FIRST ? Z0 : st[5 * F4 + idx4];
    const float4 sxy_o = FIRST ? Z0 : st[6 * F4 + idx4];
    const float4 sxz_o = FIRST ? Z0 : st[7 * F4 + idx4];
    const float4 syz_o = FIRST ? Z0 : st[8 * F4 + idx4];

    const float4 vx_z = shift_fwd(vxc, k4);
    const float4 vy_z = shift_fwd(vyc, k4);
    const float4 vz_z = shift_fwd(vzc, k4);

    const float4 exx = INVH * (vx_x - vxc);
    const float4 eyy = INVH * (vy_y - vyc);
    const float4 ezz = INVH * (vz_z - vzc);
    const float4 exy2 = INVH * ((vx_y - vxc) + (vy_x - vyc));
    const float4 exz2 = INVH * ((vx_z - vxc) + (vz_x - vzc));
    const float4 eyz2 = INVH * ((vy_z - vyc) + (vz_y - vzc));
    const float4 tr = exx + eyy + ezz;

    st[3 * F4 + idx4] = sxx_o + DTc * (lam0 * tr + (2.0f * mu0) * exx);
    st[4 * F4 + idx4] = syy_o + DTc * (lam0 * tr + (2.0f * mu0) * eyy);
    st[5 * F4 + idx4] = szz_o + DTc * (lam0 * tr + (2.0f * mu0) * ezz);
    st[6 * F4 + idx4] = sxy_o + (DTc * me) * exy2;
    st[7 * F4 + idx4] = sxz_o + (DTc * me) * exz2;
    st[8 * F4 + idx4] = syz_o + (DTc * me) * eyz2;
}

// ---- velocity update (backward differences) + source ----------------------
// FIRST: sxy==0 everywhere (exy2 was 0 in step-1 stress) and vx_old=vy_old=0.
template <bool FIRST>
__global__ __launch_bounds__(256, 5) void velocity_step_kernel(
    const float* __restrict__ rho, const float* __restrict__ damping,
    const float* __restrict__ traj, int t, int write_out, float* __restrict__ out)
{
    const int k4 = threadIdx.x;
    const int j  = blockIdx.x * 16 + threadIdx.y;
    const int i  = blockIdx.y;
    const int b  = blockIdx.z;
    const int mm4  = (i * NYC + j) * SY4 + k4;
    const int idx4 = b * M4 + mm4;

    const bool lx = (i > 0);
    const bool ly = (j > 0);
    const int ix = lx ? idx4 - SX4 : idx4;
    const int iy = ly ? idx4 - SY4 : idx4;
    const float4 Z0 = make_float4(0.f, 0.f, 0.f, 0.f);

    // Prologue: source Gaussian, damping, rho — input-only.
    const float xt = traj[(b * TC + t) * 2 + 0];
    const float yt = traj[(b * TC + t) * 2 + 1];
    const float xg = (i + 0.5f) * H, yg = (j + 0.5f) * H;
    const float axy = -((xg - xt) * (xg - xt) + (yg - yt) * (yg - yt)) * IS_XY;
    float s[4];
    #pragma unroll
    for (int c = 0; c < 4; c++) {
        float dz = (4 * k4 + c + 0.5f) * H - SRC_Z;
        float arg = axy - dz * dz * IS_Z;
        s[c] = (arg > -60.0f) ? __expf(arg) : 0.0f;
    }
    const float4 src = make_float4(s[0], s[1], s[2], s[3]);
    const float rinv = 1.0f / rho[0];
    const float4 damp = reinterpret_cast<const float4*>(damping)[mm4];
    const float4 fac = BULK * damp;

    cudaGridDependencySynchronize();

    float4* st = reinterpret_cast<float4*>(g_state);

    const float4 sxxc = st[3 * F4 + idx4];
    const float4 syyc = st[4 * F4 + idx4];
    const float4 szzc = st[5 * F4 + idx4];
    const float4 sxyc = FIRST ? Z0 : st[6 * F4 + idx4];
    const float4 sxzc = st[7 * F4 + idx4];
    const float4 syzc = st[8 * F4 + idx4];
    const float4 sxx_x = st[3 * F4 + ix];
    const float4 sxy_x = FIRST ? Z0 : st[6 * F4 + ix];
    const float4 sxz_x = st[7 * F4 + ix];
    const float4 sxy_y = FIRST ? Z0 : st[6 * F4 + iy];
    const float4 syy_y = st[4 * F4 + iy];
    const float4 syz_y = st[8 * F4 + iy];
    const float4 vx_old = FIRST ? Z0 : st[0 * F4 + idx4];
    const float4 vy_old = FIRST ? Z0 : st[1 * F4 + idx4];
    const float4 vz_old = st[2 * F4 + idx4];

    const float4 sxz_z = shift_bwd(sxzc, k4);
    const float4 syz_z = shift_bwd(syzc, k4);
    const float4 szz_z = shift_bwd(szzc, k4);

    const float4 div_x = INVH * ((sxxc - sxx_x) + (sxyc - sxy_y) + (sxzc - sxz_z));
    const float4 div_y = INVH * ((sxyc - sxy_x) + (syyc - syy_y) + (syzc - syz_z));
    const float4 div_z = INVH * ((sxzc - sxz_x) + (syzc - syz_y) + (szzc - szz_z));

    const float4 vx = (vx_old + (DTc * rinv) * div_x) * fac;
    const float4 vy = (vy_old + (DTc * rinv) * div_y) * fac;
    const float4 vz = (vz_old + (DTc * rinv) * (div_z + src)) * fac;

    st[0 * F4 + idx4] = vx;
    st[1 * F4 + idx4] = vy;
    st[2 * F4 + idx4] = vz;

    if (write_out) {
        float4* out4 = reinterpret_cast<float4*>(out);
        out4[idx4] = vz;
        float4 sm;
        sm.x = sqrtf(sxyc.x * sxyc.x + sxzc.x * sxzc.x + syzc.x * syzc.x + 1e-8f);
        sm.y = sqrtf(sxyc.y * sxyc.y + sxzc.y * sxzc.y + syzc.y * syzc.y + 1e-8f);
        sm.z = sqrtf(sxyc.z * sxyc.z + sxzc.z * sxzc.z + syzc.z * syzc.z + 1e-8f);
        sm.w = sqrtf(sxyc.w * sxyc.w + sxzc.w * sxzc.w + syzc.w * syzc.w + 1e-8f);
        out4[F4 + idx4] = sm;
    }
}

// ---- PDL launch helper ----------------------------------------------------
template <typename... Args>
static void launch_pdl(void (*kern)(Args...), dim3 grd, dim3 blk, Args... args)
{
    cudaLaunchAttribute attr[1];
    attr[0].id = cudaLaunchAttributeProgrammaticStreamSerialization;
    attr[0].val.programmaticStreamSerializationAllowed = 1;
    cudaLaunchConfig_t cfg{};
    cfg.gridDim = grd;
    cfg.blockDim = blk;
    cfg.dynamicSmemBytes = 0;
    cfg.stream = 0;
    cfg.attrs = attr;
    cfg.numAttrs = 1;
    cudaLaunchKernelEx(&cfg, kern, args...);
}

extern "C" void kernel_launch(void* const* d_in, const int* in_sizes, int n_in,
                              void* d_out, int out_size)
{
    // metadata order: trajectory, grid_x, grid_y, grid_z, rho, mu, lam, eta, damping
    const float* traj    = (const float*)d_in[0];
    const float* rho     = (const float*)d_in[4];
    const float* mu      = (const float*)d_in[5];
    const float* lam     = (const float*)d_in[6];
    const float* eta     = (const float*)d_in[7];
    const float* damping = (const float*)d_in[8];
    float* out = (float*)d_out;

    dim3 blk(16, 16, 1);
    dim3 grd(NYC / 16, NXC, BC);

    init_step_kernel<<<grd, blk>>>(rho, damping, traj);

    for (int t = 1; t < TC; t++) {
        const int wo = (t == TC - 1) ? 1 : 0;
        if (t == 1) {
            launch_pdl(stress_step_kernel<true>, grd, blk, lam, mu, eta);
            launch_pdl(velocity_step_kernel<true>, grd, blk,
                       rho, damping, traj, t, wo, out);
        } else {
            launch_pdl(stress_step_kernel<false>, grd, blk, lam, mu, eta);
            launch_pdl(velocity_step_kernel<false>, grd, blk,
                       rho, damping, traj, t, wo, out);
        }
    }
}